// round 16
// baseline (speedup 1.0000x reference)
#include <cuda_runtime.h>
#include <math.h>
#include <stdint.h>

#define NN 100000
#define EE 800000
#define FD 128   // H * C
#define KD 64    // input/output dim of each GEMM
#define EDD 32   // edge attr dim
#define HH 2     // heads
#define SCB 98   // ceil(NN / 1024) scan blocks

#define FMA2(d, a, b, c) \
    asm("fma.rn.f32x2 %0, %1, %2, %3;" : "=l"(d) : "l"(a), "l"(b), "l"(c))

__device__ __forceinline__ float2 unpack2(unsigned long long v) {
    float2 r;
    asm("mov.b64 {%0, %1}, %2;" : "=f"(r.x), "=f"(r.y) : "l"(v));
    return r;
}

__device__ __forceinline__ unsigned long long dup2(float v) {
    unsigned long long r;
    asm("mov.b64 %0, {%1, %2};" : "=l"(r) : "f"(v), "f"(v));
    return r;
}

// ---------------- scratch (device globals) -----------------------------------
__device__ int   g_degi[NN];
__device__ int   g_dcnt[NN];
__device__ int   g_cur[NN];
__device__ int   g_doff[NN + 1];
__device__ int   g_part[128];
__device__ float g_dn1[NN];
__device__ float g_dn2[NN];
__device__ float g_Wq[FD * KD];    // layer-1 quantized weights
__device__ float g_Wq2[FD * KD];   // layer-2 quantized weights
__device__ float4 g_ed1[EE];       // (src, ae0, ae1, -) layer 1, CSR order
__device__ float4 g_ed2[EE];       // (src, ae0, ae1, -) layer 2, CSR order
__device__ float g_h[NN * FD];     // 51.2 MB (fp32: quant-boundary sensitivity
                                   //  makes compressed h structurally unsafe)
__device__ float g_asrc[NN * HH];
__device__ float g_adst[NN * HH];
__device__ float g_x2[NN * KD];    // 25.6 MB
__device__ int   g_imax[2];

// ---------------- degree -----------------------------------------------------
__global__ void k_deg(const int* __restrict__ src, const int* __restrict__ dst) {
    int e = blockIdx.x * blockDim.x + threadIdx.x;
    if (e < EE) {
        atomicAdd(&g_degi[src[e]], 1);
        atomicAdd(&g_dcnt[dst[e]], 1);
    }
}

// fused: degree-norm (blocks 0..gN-1) + W1 fake-quant (last block)
__global__ void k_prep(const float* __restrict__ a1, const float* __restrict__ a2,
                       const float* __restrict__ w, int gN) {
    if ((int)blockIdx.x < gN) {
        int n = blockIdx.x * blockDim.x + threadIdx.x;
        if (n < NN) {
            float d = (float)(g_degi[n] + 1);
            g_dn1[n] = powf(d, -a1[0]);
            g_dn2[n] = powf(d, -a2[0]);
        }
        return;
    }
    __shared__ float sm[256];
    float m = 0.f;
    for (int i = threadIdx.x; i < FD * KD; i += 256) m = fmaxf(m, fabsf(w[i]));
    sm[threadIdx.x] = m;
    __syncthreads();
    for (int s = 128; s > 0; s >>= 1) {
        if (threadIdx.x < s) sm[threadIdx.x] = fmaxf(sm[threadIdx.x], sm[threadIdx.x + s]);
        __syncthreads();
    }
    __shared__ float ssc;
    if (threadIdx.x == 0) {
        ssc = fmaxf(sm[0], 1e-8f) / 127.0f;
        g_imax[0] = 0;
    }
    __syncthreads();
    float s = ssc;
    for (int i = threadIdx.x; i < FD * KD; i += 256) {
        float q = rintf(w[i] / s);
        q = fminf(fmaxf(q, -128.f), 127.f);
        g_Wq[i] = q * s;
    }
}

// ---------------- multi-block exclusive scan ---------------------------------
__global__ void k_scan1() {
    int b = blockIdx.x, t = threadIdx.x;
    int i0 = b * 1024 + t * 4;
    int s = 0;
#pragma unroll
    for (int j = 0; j < 4; j++) { int i = i0 + j; if (i < NN) s += g_dcnt[i]; }
    __shared__ int sm[256];
    sm[t] = s; __syncthreads();
    for (int o = 128; o; o >>= 1) { if (t < o) sm[t] += sm[t + o]; __syncthreads(); }
    if (t == 0) g_part[b] = sm[0];
    if (b == 0 && t == 0) g_doff[NN] = EE;
}

__global__ void k_scan2() {
    int t = threadIdx.x;
    int v = (t < SCB) ? g_part[t] : 0;
    __shared__ int sm[128];
    sm[t] = v; __syncthreads();
    for (int o = 1; o < 128; o <<= 1) {
        int u = (t >= o) ? sm[t - o] : 0;
        __syncthreads(); sm[t] += u; __syncthreads();
    }
    if (t < SCB) g_part[t] = sm[t] - v;
}

__global__ void k_scan3() {
    int b = blockIdx.x, t = threadIdx.x;
    int i0 = b * 1024 + t * 4;
    int v[4]; int s = 0;
#pragma unroll
    for (int j = 0; j < 4; j++) {
        int i = i0 + j;
        v[j] = (i < NN) ? g_dcnt[i] : 0;
        s += v[j];
    }
    __shared__ int sm[256];
    sm[t] = s; __syncthreads();
    for (int o = 1; o < 256; o <<= 1) {
        int u = (t >= o) ? sm[t - o] : 0;
        __syncthreads(); sm[t] += u; __syncthreads();
    }
    int run = g_part[b] + sm[t] - s;
#pragma unroll
    for (int j = 0; j < 4; j++) {
        int i = i0 + j;
        if (i < NN) g_doff[i] = run;
        run += v[j];
    }
}

// ---------------- fused fake-quant of W2 (branch B, single block) ------------
__global__ void k_quantW2(const float* __restrict__ w, int slot) {
    __shared__ float sm[256];
    float m = 0.f;
    for (int i = threadIdx.x; i < FD * KD; i += 256) m = fmaxf(m, fabsf(w[i]));
    sm[threadIdx.x] = m;
    __syncthreads();
    for (int s = 128; s > 0; s >>= 1) {
        if (threadIdx.x < s) sm[threadIdx.x] = fmaxf(sm[threadIdx.x], sm[threadIdx.x + s]);
        __syncthreads();
    }
    __shared__ float ssc;
    if (threadIdx.x == 0) {
        ssc = fmaxf(sm[0], 1e-8f) / 127.0f;
        g_imax[slot] = 0;
    }
    __syncthreads();
    float s = ssc;
    for (int i = threadIdx.x; i < FD * KD; i += 256) {
        float q = rintf(w[i] / s);
        q = fminf(fmaxf(q, -128.f), 127.f);
        g_Wq2[i] = q * s;
    }
}

// ---------------- fused edge precompute + CSR fill ----------------------------
__global__ __launch_bounds__(256) void k_edgepre(
        const float* __restrict__ ea, const int* __restrict__ src,
        const int* __restrict__ dst,
        const float* __restrict__ We1, const float* __restrict__ ae1,
        const float* __restrict__ We2, const float* __restrict__ ae2) {
    __shared__ float r1[64][4];
    __shared__ float r2[64][4];
    __shared__ float sv1[HH * EDD];
    __shared__ float sv2[HH * EDD];
    {
        int t = threadIdx.x;
        int i = t >> 2, j = t & 3;
        int h = i / EDD, d = i % EDD;
        float s1 = 0.f, s2 = 0.f;
        for (int c = j * 16; c < j * 16 + 16; c++) {
            s1 += ae1[h * 64 + c] * We1[(h * 64 + c) * EDD + d];
            s2 += ae2[h * 64 + c] * We2[(h * 64 + c) * EDD + d];
        }
        r1[i][j] = s1; r2[i][j] = s2;
        __syncthreads();
        if (j == 0) {
            sv1[i] = r1[i][0] + r1[i][1] + r1[i][2] + r1[i][3];
            sv2[i] = r2[i][0] + r2[i][1] + r2[i][2] + r2[i][3];
        }
        __syncthreads();
    }
    int e = blockIdx.x * blockDim.x + threadIdx.x;
    if (e >= EE) return;
    const float4* p = (const float4*)(ea + (size_t)e * EDD);
    float a0 = 0.f, a1 = 0.f, b0 = 0.f, b1 = 0.f;
#pragma unroll
    for (int i = 0; i < 8; i++) {
        float4 q = p[i];
        a0 += q.x * sv1[i*4] + q.y * sv1[i*4+1] + q.z * sv1[i*4+2] + q.w * sv1[i*4+3];
        a1 += q.x * sv1[32+i*4] + q.y * sv1[32+i*4+1] + q.z * sv1[32+i*4+2] + q.w * sv1[32+i*4+3];
        b0 += q.x * sv2[i*4] + q.y * sv2[i*4+1] + q.z * sv2[i*4+2] + q.w * sv2[i*4+3];
        b1 += q.x * sv2[32+i*4] + q.y * sv2[32+i*4+1] + q.z * sv2[32+i*4+2] + q.w * sv2[32+i*4+3];
    }
    int d = dst[e];
    int pos = g_doff[d] + atomicAdd(&g_cur[d], 1);
    float sf = __int_as_float(src[e]);
    g_ed1[pos] = make_float4(sf, a0, a1, 0.f);
    g_ed2[pos] = make_float4(sf, b0, b1, 0.f);
}

// ---------------- 8x8 register-blocked FFMA2 GEMM (R12/R14 form, proven) -----
__global__ __launch_bounds__(256, 2) void k_gemm(const float* __restrict__ xin_or_null,
                                                 int layer,
                                                 const float* __restrict__ as_g,
                                                 const float* __restrict__ ad_g) {
    __shared__ float sW[33 * 128];      // [k][o]
    __shared__ float sX[33 * 128];      // [k][node]
    __shared__ float sas[FD], sad[FD];

    const float* xin = xin_or_null ? xin_or_null : g_x2;
    const float* dn = (layer == 1) ? g_dn1 : g_dn2;
    const float* wq = (layer == 1) ? g_Wq : g_Wq2;
    float qs = 0.f;
    if (layer == 2) qs = fmaxf(__int_as_float(g_imax[0]), 1e-8f) * (1.f / 127.f);

    int t = threadIdx.x;
    int nb = blockIdx.x * 128;
    if (t < FD) { sas[t] = as_g[t]; sad[t] = ad_g[t]; }

    int tx = t & 15, ty = t >> 4;
    int ob = tx * 8;
    int nloc = ty * 8;

    unsigned long long acc[8][4];
#pragma unroll
    for (int i = 0; i < 8; i++)
#pragma unroll
        for (int p = 0; p < 4; p++) acc[i][p] = 0ull;

    for (int stage = 0; stage < 2; stage++) {
        if (stage) __syncthreads();
#pragma unroll
        for (int rep = 0; rep < 4; rep++) {
            int i = t + rep * 256;
            int o = i & 127, kq = i >> 7;
            float4 w4 = ((const float4*)wq)[o * 16 + stage * 8 + kq];
            sW[(kq*4+0)*128 + o] = w4.x;
            sW[(kq*4+1)*128 + o] = w4.y;
            sW[(kq*4+2)*128 + o] = w4.z;
            sW[(kq*4+3)*128 + o] = w4.w;
        }
#pragma unroll
        for (int rep = 0; rep < 4; rep++) {
            int i = t + rep * 256;
            int nl = i & 127, kq = i >> 7;
            int n = nb + nl;
            float4 v = make_float4(0.f, 0.f, 0.f, 0.f);
            if (n < NN) {
                v = ((const float4*)(xin + (size_t)n * KD))[stage * 8 + kq];
                if (layer == 2) {
                    float q;
                    q = rintf(v.x/qs); v.x = fmaxf(fminf(fmaxf(q,-128.f),127.f)*qs, 0.f);
                    q = rintf(v.y/qs); v.y = fmaxf(fminf(fmaxf(q,-128.f),127.f)*qs, 0.f);
                    q = rintf(v.z/qs); v.z = fmaxf(fminf(fmaxf(q,-128.f),127.f)*qs, 0.f);
                    q = rintf(v.w/qs); v.w = fmaxf(fminf(fmaxf(q,-128.f),127.f)*qs, 0.f);
                }
                float dd = dn[n];
                v.x *= dd; v.y *= dd; v.z *= dd; v.w *= dd;
            }
            sX[(kq*4+0)*128 + nl] = v.x;
            sX[(kq*4+1)*128 + nl] = v.y;
            sX[(kq*4+2)*128 + nl] = v.z;
            sX[(kq*4+3)*128 + nl] = v.w;
        }
        __syncthreads();

        float4 xa = *(const float4*)&sX[nloc];
        float4 xb = *(const float4*)&sX[nloc + 4];
        ulonglong2 wa = *(const ulonglong2*)&sW[ob];
        ulonglong2 wb = *(const ulonglong2*)&sW[ob + 4];

#pragma unroll 8
        for (int k = 0; k < 32; k++) {
            float4 xan = *(const float4*)&sX[(k+1)*128 + nloc];
            float4 xbn = *(const float4*)&sX[(k+1)*128 + nloc + 4];
            ulonglong2 wan = *(const ulonglong2*)&sW[(k+1)*128 + ob];
            ulonglong2 wbn = *(const ulonglong2*)&sW[(k+1)*128 + ob + 4];

            unsigned long long x0 = dup2(xa.x), x1 = dup2(xa.y);
            unsigned long long x2 = dup2(xa.z), x3 = dup2(xa.w);
            unsigned long long x4 = dup2(xb.x), x5 = dup2(xb.y);
            unsigned long long x6 = dup2(xb.z), x7 = dup2(xb.w);
            FMA2(acc[0][0], x0, wa.x, acc[0][0]); FMA2(acc[0][1], x0, wa.y, acc[0][1]);
            FMA2(acc[0][2], x0, wb.x, acc[0][2]); FMA2(acc[0][3], x0, wb.y, acc[0][3]);
            FMA2(acc[1][0], x1, wa.x, acc[1][0]); FMA2(acc[1][1], x1, wa.y, acc[1][1]);
            FMA2(acc[1][2], x1, wb.x, acc[1][2]); FMA2(acc[1][3], x1, wb.y, acc[1][3]);
            FMA2(acc[2][0], x2, wa.x, acc[2][0]); FMA2(acc[2][1], x2, wa.y, acc[2][1]);
            FMA2(acc[2][2], x2, wb.x, acc[2][2]); FMA2(acc[2][3], x2, wb.y, acc[2][3]);
            FMA2(acc[3][0], x3, wa.x, acc[3][0]); FMA2(acc[3][1], x3, wa.y, acc[3][1]);
            FMA2(acc[3][2], x3, wb.x, acc[3][2]); FMA2(acc[3][3], x3, wb.y, acc[3][3]);
            FMA2(acc[4][0], x4, wa.x, acc[4][0]); FMA2(acc[4][1], x4, wa.y, acc[4][1]);
            FMA2(acc[4][2], x4, wb.x, acc[4][2]); FMA2(acc[4][3], x4, wb.y, acc[4][3]);
            FMA2(acc[5][0], x5, wa.x, acc[5][0]); FMA2(acc[5][1], x5, wa.y, acc[5][1]);
            FMA2(acc[5][2], x5, wb.x, acc[5][2]); FMA2(acc[5][3], x5, wb.y, acc[5][3]);
            FMA2(acc[6][0], x6, wa.x, acc[6][0]); FMA2(acc[6][1], x6, wa.y, acc[6][1]);
            FMA2(acc[6][2], x6, wb.x, acc[6][2]); FMA2(acc[6][3], x6, wb.y, acc[6][3]);
            FMA2(acc[7][0], x7, wa.x, acc[7][0]); FMA2(acc[7][1], x7, wa.y, acc[7][1]);
            FMA2(acc[7][2], x7, wb.x, acc[7][2]); FMA2(acc[7][3], x7, wb.y, acc[7][3]);

            xa = xan; xb = xbn; wa = wan; wb = wbn;
        }
    }

    float av[8], dv[8];
#pragma unroll
    for (int j = 0; j < 8; j++) { av[j] = sas[ob + j]; dv[j] = sad[ob + j]; }

    float ps[8], pd[8];
#pragma unroll
    for (int i = 0; i < 8; i++) {
        int n = nb + nloc + i;
        float2 u0 = unpack2(acc[i][0]), u1 = unpack2(acc[i][1]);
        float2 u2 = unpack2(acc[i][2]), u3 = unpack2(acc[i][3]);
        if (n < NN) {
            float4* hp = (float4*)&g_h[(size_t)n * FD + ob];
            hp[0] = make_float4(u0.x, u0.y, u1.x, u1.y);
            hp[1] = make_float4(u2.x, u2.y, u3.x, u3.y);
        }
        ps[i] = u0.x*av[0] + u0.y*av[1] + u1.x*av[2] + u1.y*av[3]
              + u2.x*av[4] + u2.y*av[5] + u3.x*av[6] + u3.y*av[7];
        pd[i] = u0.x*dv[0] + u0.y*dv[1] + u1.x*dv[2] + u1.y*dv[3]
              + u2.x*dv[4] + u2.y*dv[5] + u3.x*dv[6] + u3.y*dv[7];
    }

#pragma unroll
    for (int o = 1; o <= 4; o <<= 1) {
#pragma unroll
        for (int i = 0; i < 8; i++) {
            ps[i] += __shfl_xor_sync(0xffffffffu, ps[i], o);
            pd[i] += __shfl_xor_sync(0xffffffffu, pd[i], o);
        }
    }
    if ((tx & 7) == 0) {
        int h = tx >> 3;
#pragma unroll
        for (int i = 0; i < 8; i++) {
            int n = nb + nloc + i;
            if (n < NN) { g_asrc[n*2+h] = ps[i]; g_adst[n*2+h] = pd[i]; }
        }
    }
}

// ---------------- gather: 2 nodes per warp, fp32 h, 4-edge unrolled ----------
__global__ __launch_bounds__(256) void k_gather(int layer, const float* __restrict__ bias) {
    const float4* ed = (layer == 1) ? g_ed1 : g_ed2;
    int tid  = threadIdx.x;
    int warp = tid >> 5;
    int lane = tid & 31;
    int half = lane >> 4;
    int hl   = lane & 15;
    unsigned mask = half ? 0xffff0000u : 0x0000ffffu;
    int node = (blockIdx.x * 256 + tid) >> 4;
    int sbase = half * 16;

    __shared__ int   sm_s [8][32];
    __shared__ float sm_e0[8][32];
    __shared__ float sm_e1[8][32];

    int beg = g_doff[node];
    int deg = g_doff[node + 1] - beg;
    float2 ad = ((const float2*)g_adst)[node];

    float den0 = 0.f, den1 = 0.f;
    float4 A0 = make_float4(0.f, 0.f, 0.f, 0.f);
    float4 A1 = make_float4(0.f, 0.f, 0.f, 0.f);

    const int*   ss = sm_s [warp] + sbase;
    const float* s0p = sm_e0[warp] + sbase;
    const float* s1p = sm_e1[warp] + sbase;

    for (int base = 0; base < deg; base += 16) {
        int cnt = min(16, deg - base);
        int s = 0; float e0 = 0.f, e1 = 0.f;
        if (hl < cnt) {
            float4 er = ed[beg + base + hl];
            s = __float_as_int(er.x);
            float2 as = ((const float2*)g_asrc)[s];
            float x0 = as.x + ad.x + er.y; x0 = (x0 >= 0.f) ? x0 : 0.2f * x0;
            float x1 = as.y + ad.y + er.z; x1 = (x1 >= 0.f) ? x1 : 0.2f * x1;
            e0 = __expf(x0);
            e1 = __expf(x1);
        }
        den0 += e0; den1 += e1;
        sm_s [warp][sbase + hl] = s;
        sm_e0[warp][sbase + hl] = e0;
        sm_e1[warp][sbase + hl] = e1;
        __syncwarp(mask);
        int k = 0;
        for (; k + 4 <= cnt; k += 4) {          // 8 independent LDG.128 in flight
            int sA = ss[k],   sB = ss[k+1], sC = ss[k+2], sD = ss[k+3];
            float wA0 = s0p[k],   wA1 = s1p[k];
            float wB0 = s0p[k+1], wB1 = s1p[k+1];
            float wC0 = s0p[k+2], wC1 = s1p[k+2];
            float wD0 = s0p[k+3], wD1 = s1p[k+3];
            const float4* hA = (const float4*)(g_h + (size_t)sA * FD);
            const float4* hB = (const float4*)(g_h + (size_t)sB * FD);
            const float4* hC = (const float4*)(g_h + (size_t)sC * FD);
            const float4* hD = (const float4*)(g_h + (size_t)sD * FD);
            float4 pA = hA[hl], qA = hA[16 + hl];
            float4 pB = hB[hl], qB = hB[16 + hl];
            float4 pC = hC[hl], qC = hC[16 + hl];
            float4 pD = hD[hl], qD = hD[16 + hl];
            A0.x += wA0*pA.x + wB0*pB.x + wC0*pC.x + wD0*pD.x;
            A0.y += wA0*pA.y + wB0*pB.y + wC0*pC.y + wD0*pD.y;
            A0.z += wA0*pA.z + wB0*pB.z + wC0*pC.z + wD0*pD.z;
            A0.w += wA0*pA.w + wB0*pB.w + wC0*pC.w + wD0*pD.w;
            A1.x += wA1*qA.x + wB1*qB.x + wC1*qC.x + wD1*qD.x;
            A1.y += wA1*qA.y + wB1*qB.y + wC1*qC.y + wD1*qD.y;
            A1.z += wA1*qA.z + wB1*qB.z + wC1*qC.z + wD1*qD.z;
            A1.w += wA1*qA.w + wB1*qB.w + wC1*qC.w + wD1*qD.w;
        }
        for (; k < cnt; k++) {
            int   sk = ss[k];
            float w0 = s0p[k], w1 = s1p[k];
            const float4* hp = (const float4*)(g_h + (size_t)sk * FD);
            float4 p = hp[hl], q = hp[16 + hl];
            A0.x += w0*p.x; A0.y += w0*p.y; A0.z += w0*p.z; A0.w += w0*p.w;
            A1.x += w1*q.x; A1.y += w1*q.y; A1.z += w1*q.z; A1.w += w1*q.w;
        }
        __syncwarp(mask);
    }

#pragma unroll
    for (int o = 8; o; o >>= 1) {
        den0 += __shfl_xor_sync(mask, den0, o);
        den1 += __shfl_xor_sync(mask, den1, o);
    }
    float inv0 = 1.f / (den0 + 1e-16f);
    float inv1 = 1.f / (den1 + 1e-16f);

    float4 bb = ((const float4*)bias)[hl];
    float4 tv;
    tv.x = (A0.x * inv0 + A1.x * inv1) * 0.5f + bb.x;
    tv.y = (A0.y * inv0 + A1.y * inv1) * 0.5f + bb.y;
    tv.z = (A0.z * inv0 + A1.z * inv1) * 0.5f + bb.z;
    tv.w = (A0.w * inv0 + A1.w * inv1) * 0.5f + bb.w;
    ((float4*)(g_x2 + (size_t)node * KD))[hl] = tv;
    float mv = fmaxf(fmaxf(fabsf(tv.x), fabsf(tv.y)), fmaxf(fabsf(tv.z), fabsf(tv.w)));

    __syncwarp();
#pragma unroll
    for (int o = 16; o; o >>= 1) mv = fmaxf(mv, __shfl_xor_sync(0xffffffffu, mv, o));

    __shared__ float sred[8];
    if (lane == 0) sred[warp] = mv;
    __syncthreads();
    if (tid < 8) {
        float v = sred[tid];
#pragma unroll
        for (int o = 4; o; o >>= 1) v = fmaxf(v, __shfl_xor_sync(0xffu, v, o));
        if (tid == 0) atomicMax(&g_imax[layer - 1], __float_as_int(v));
    }
}

// ---------------- final per-tensor fake-quant (float4 vectorized) ------------
__global__ void k_fin_post(float4* __restrict__ out) {
    int i = blockIdx.x * blockDim.x + threadIdx.x;
    if (i >= NN * KD / 4) return;
    float s = fmaxf(__int_as_float(g_imax[1]), 1e-8f) * (1.f / 127.f);
    float4 v = ((const float4*)g_x2)[i];
    float q;
    q = rintf(v.x / s); v.x = fminf(fmaxf(q, -128.f), 127.f) * s;
    q = rintf(v.y / s); v.y = fminf(fmaxf(q, -128.f), 127.f) * s;
    q = rintf(v.z / s); v.z = fminf(fmaxf(q, -128.f), 127.f) * s;
    q = rintf(v.w / s); v.w = fminf(fmaxf(q, -128.f), 127.f) * s;
    out[i] = v;
}

// ---------------- host ------------------------------------------------------
extern "C" void kernel_launch(void* const* d_in, const int* in_sizes, int n_in,
                              void* d_out, int out_size) {
    const float* x    = (const float*)d_in[0];
    const int*   ei   = (const int*)d_in[1];
    const int*   src  = ei;
    const int*   dst  = ei + EE;
    const float* ea   = (const float*)d_in[2];
    const float* a1   = (const float*)d_in[3];
    const float* W1   = (const float*)d_in[4];
    const float* We1  = (const float*)d_in[5];
    const float* as1  = (const float*)d_in[6];
    const float* ad1  = (const float*)d_in[7];
    const float* ae1  = (const float*)d_in[8];
    const float* b1   = (const float*)d_in[9];
    const float* a2   = (const float*)d_in[10];
    const float* W2   = (const float*)d_in[11];
    const float* We2  = (const float*)d_in[12];
    const float* as2  = (const float*)d_in[13];
    const float* ad2  = (const float*)d_in[14];
    const float* ae2  = (const float*)d_in[15];
    const float* b2   = (const float*)d_in[16];
    float* out = (float*)d_out;

    const int TB = 256;
    int gN   = (NN + TB - 1) / TB;
    int gE   = (EE + TB - 1) / TB;
    int gGem = (NN + 127) / 128;
    int gGat = NN / 16;
    int gF4  = (NN * KD / 4 + TB - 1) / TB;

    cudaStream_t sB;
    cudaStreamCreateWithFlags(&sB, cudaStreamNonBlocking);
    cudaEvent_t evDeg, evB;
    cudaEventCreateWithFlags(&evDeg, cudaEventDisableTiming);
    cudaEventCreateWithFlags(&evB, cudaEventDisableTiming);

    // zero counters via memset nodes (capture-legal)
    int* dDegi; cudaGetSymbolAddress((void**)&dDegi, g_degi);
    int* dDcnt; cudaGetSymbolAddress((void**)&dDcnt, g_dcnt);
    int* dCur;  cudaGetSymbolAddress((void**)&dCur,  g_cur);
    cudaMemsetAsync(dDegi, 0, NN * sizeof(int), 0);
    cudaMemsetAsync(dDcnt, 0, NN * sizeof(int), 0);
    cudaMemsetAsync(dCur,  0, NN * sizeof(int), 0);

    // main stream: degree + layer-1 GEMM chain
    k_deg<<<gE, TB>>>(src, dst);
    cudaEventRecord(evDeg, 0);
    cudaStreamWaitEvent(sB, evDeg, 0);

    k_prep<<<gN + 1, TB>>>(a1, a2, W1, gN);
    k_gemm<<<gGem, 256>>>(x, 1, as1, ad1);              // profile anchor

    // branch B (concurrent with prep+gemm1)
    k_scan1<<<SCB, 256, 0, sB>>>();
    k_scan2<<<1, 128, 0, sB>>>();
    k_scan3<<<SCB, 256, 0, sB>>>();
    k_edgepre<<<gE, TB, 0, sB>>>(ea, src, dst, We1, ae1, We2, ae2);
    k_quantW2<<<1, 256, 0, sB>>>(W2, 1);
    cudaEventRecord(evB, sB);

    cudaStreamWaitEvent(0, evB, 0);
    k_gather<<<gGat, 256>>>(1, b1);
    k_gemm<<<gGem, 256>>>(nullptr, 2, as2, ad2);
    k_gather<<<gGat, 256>>>(2, b2);
    k_fin_post<<<gF4, TB>>>((float4*)out);
}

// round 17
// speedup vs baseline: 1.0979x; 1.0979x over previous
#include <cuda_runtime.h>
#include <math.h>
#include <stdint.h>

#define NN 100000
#define EE 800000
#define FD 128   // H * C
#define KD 64    // input/output dim of each GEMM
#define EDD 32   // edge attr dim
#define HH 2     // heads
#define SCB 98   // ceil(NN / 1024) scan blocks

#define FMA2(d, a, b, c) \
    asm("fma.rn.f32x2 %0, %1, %2, %3;" : "=l"(d) : "l"(a), "l"(b), "l"(c))

__device__ __forceinline__ float2 unpack2(unsigned long long v) {
    float2 r;
    asm("mov.b64 {%0, %1}, %2;" : "=f"(r.x), "=f"(r.y) : "l"(v));
    return r;
}

__device__ __forceinline__ unsigned long long dup2(float v) {
    unsigned long long r;
    asm("mov.b64 %0, {%1, %2};" : "=l"(r) : "f"(v), "f"(v));
    return r;
}

// ---------------- scratch (device globals) -----------------------------------
__device__ int   g_degi[NN];
__device__ int   g_dcnt[NN];
__device__ int   g_cur[NN];
__device__ int   g_doff[NN + 1];
__device__ int   g_part[128];
__device__ float g_dn1[NN];
__device__ float g_dn2[NN];
__device__ float g_Wq[FD * KD];    // layer-1 quantized weights
__device__ float g_Wq2[FD * KD];   // layer-2 quantized weights
__device__ float4 g_ed1[EE];       // (src, ae0, ae1, -) layer 1, CSR order
__device__ float4 g_ed2[EE];       // (src, ae0, ae1, -) layer 2, CSR order
__device__ float g_h[NN * FD];     // 51.2 MB fp32 (compressed h is unsafe here)
__device__ float g_asrc[NN * HH];
__device__ float g_adst[NN * HH];
__device__ float g_x2[NN * KD];    // 25.6 MB
__device__ int   g_imax[2];

// ---------------- degree -----------------------------------------------------
__global__ void k_deg(const int* __restrict__ src, const int* __restrict__ dst) {
    int e = blockIdx.x * blockDim.x + threadIdx.x;
    if (e < EE) {
        atomicAdd(&g_degi[src[e]], 1);
        atomicAdd(&g_dcnt[dst[e]], 1);
    }
}

// fused: degree-norm (blocks 0..gN-1) + W1 fake-quant (last block)
__global__ void k_prep(const float* __restrict__ a1, const float* __restrict__ a2,
                       const float* __restrict__ w, int gN) {
    if ((int)blockIdx.x < gN) {
        int n = blockIdx.x * blockDim.x + threadIdx.x;
        if (n < NN) {
            float d = (float)(g_degi[n] + 1);
            g_dn1[n] = powf(d, -a1[0]);
            g_dn2[n] = powf(d, -a2[0]);
        }
        return;
    }
    __shared__ float sm[256];
    float m = 0.f;
    for (int i = threadIdx.x; i < FD * KD; i += 256) m = fmaxf(m, fabsf(w[i]));
    sm[threadIdx.x] = m;
    __syncthreads();
    for (int s = 128; s > 0; s >>= 1) {
        if (threadIdx.x < s) sm[threadIdx.x] = fmaxf(sm[threadIdx.x], sm[threadIdx.x + s]);
        __syncthreads();
    }
    __shared__ float ssc;
    if (threadIdx.x == 0) {
        ssc = fmaxf(sm[0], 1e-8f) / 127.0f;
        g_imax[0] = 0;
    }
    __syncthreads();
    float s = ssc;
    for (int i = threadIdx.x; i < FD * KD; i += 256) {
        float q = rintf(w[i] / s);
        q = fminf(fmaxf(q, -128.f), 127.f);
        g_Wq[i] = q * s;
    }
}

// ---------------- multi-block exclusive scan ---------------------------------
__global__ void k_scan1() {
    int b = blockIdx.x, t = threadIdx.x;
    int i0 = b * 1024 + t * 4;
    int s = 0;
#pragma unroll
    for (int j = 0; j < 4; j++) { int i = i0 + j; if (i < NN) s += g_dcnt[i]; }
    __shared__ int sm[256];
    sm[t] = s; __syncthreads();
    for (int o = 128; o; o >>= 1) { if (t < o) sm[t] += sm[t + o]; __syncthreads(); }
    if (t == 0) g_part[b] = sm[0];
    if (b == 0 && t == 0) g_doff[NN] = EE;
}

__global__ void k_scan2() {
    int t = threadIdx.x;
    int v = (t < SCB) ? g_part[t] : 0;
    __shared__ int sm[128];
    sm[t] = v; __syncthreads();
    for (int o = 1; o < 128; o <<= 1) {
        int u = (t >= o) ? sm[t - o] : 0;
        __syncthreads(); sm[t] += u; __syncthreads();
    }
    if (t < SCB) g_part[t] = sm[t] - v;
}

__global__ void k_scan3() {
    int b = blockIdx.x, t = threadIdx.x;
    int i0 = b * 1024 + t * 4;
    int v[4]; int s = 0;
#pragma unroll
    for (int j = 0; j < 4; j++) {
        int i = i0 + j;
        v[j] = (i < NN) ? g_dcnt[i] : 0;
        s += v[j];
    }
    __shared__ int sm[256];
    sm[t] = s; __syncthreads();
    for (int o = 1; o < 256; o <<= 1) {
        int u = (t >= o) ? sm[t - o] : 0;
        __syncthreads(); sm[t] += u; __syncthreads();
    }
    int run = g_part[b] + sm[t] - s;
#pragma unroll
    for (int j = 0; j < 4; j++) {
        int i = i0 + j;
        if (i < NN) g_doff[i] = run;
        run += v[j];
    }
}

// ---------------- fused fake-quant of W2 (branch B, single block) ------------
__global__ void k_quantW2(const float* __restrict__ w, int slot) {
    __shared__ float sm[256];
    float m = 0.f;
    for (int i = threadIdx.x; i < FD * KD; i += 256) m = fmaxf(m, fabsf(w[i]));
    sm[threadIdx.x] = m;
    __syncthreads();
    for (int s = 128; s > 0; s >>= 1) {
        if (threadIdx.x < s) sm[threadIdx.x] = fmaxf(sm[threadIdx.x], sm[threadIdx.x + s]);
        __syncthreads();
    }
    __shared__ float ssc;
    if (threadIdx.x == 0) {
        ssc = fmaxf(sm[0], 1e-8f) / 127.0f;
        g_imax[slot] = 0;
    }
    __syncthreads();
    float s = ssc;
    for (int i = threadIdx.x; i < FD * KD; i += 256) {
        float q = rintf(w[i] / s);
        q = fminf(fmaxf(q, -128.f), 127.f);
        g_Wq2[i] = q * s;
    }
}

// ---------------- fused edge precompute + CSR fill ----------------------------
__global__ __launch_bounds__(256) void k_edgepre(
        const float* __restrict__ ea, const int* __restrict__ src,
        const int* __restrict__ dst,
        const float* __restrict__ We1, const float* __restrict__ ae1,
        const float* __restrict__ We2, const float* __restrict__ ae2) {
    __shared__ float r1[64][4];
    __shared__ float r2[64][4];
    __shared__ float sv1[HH * EDD];
    __shared__ float sv2[HH * EDD];
    {
        int t = threadIdx.x;
        int i = t >> 2, j = t & 3;
        int h = i / EDD, d = i % EDD;
        float s1 = 0.f, s2 = 0.f;
        for (int c = j * 16; c < j * 16 + 16; c++) {
            s1 += ae1[h * 64 + c] * We1[(h * 64 + c) * EDD + d];
            s2 += ae2[h * 64 + c] * We2[(h * 64 + c) * EDD + d];
        }
        r1[i][j] = s1; r2[i][j] = s2;
        __syncthreads();
        if (j == 0) {
            sv1[i] = r1[i][0] + r1[i][1] + r1[i][2] + r1[i][3];
            sv2[i] = r2[i][0] + r2[i][1] + r2[i][2] + r2[i][3];
        }
        __syncthreads();
    }
    int e = blockIdx.x * blockDim.x + threadIdx.x;
    if (e >= EE) return;
    const float4* p = (const float4*)(ea + (size_t)e * EDD);
    float a0 = 0.f, a1 = 0.f, b0 = 0.f, b1 = 0.f;
#pragma unroll
    for (int i = 0; i < 8; i++) {
        float4 q = p[i];
        a0 += q.x * sv1[i*4] + q.y * sv1[i*4+1] + q.z * sv1[i*4+2] + q.w * sv1[i*4+3];
        a1 += q.x * sv1[32+i*4] + q.y * sv1[32+i*4+1] + q.z * sv1[32+i*4+2] + q.w * sv1[32+i*4+3];
        b0 += q.x * sv2[i*4] + q.y * sv2[i*4+1] + q.z * sv2[i*4+2] + q.w * sv2[i*4+3];
        b1 += q.x * sv2[32+i*4] + q.y * sv2[32+i*4+1] + q.z * sv2[32+i*4+2] + q.w * sv2[32+i*4+3];
    }
    int d = dst[e];
    int pos = g_doff[d] + atomicAdd(&g_cur[d], 1);
    float sf = __int_as_float(src[e]);
    g_ed1[pos] = make_float4(sf, a0, a1, 0.f);
    g_ed2[pos] = make_float4(sf, b0, b1, 0.f);
}

// ---------------- 8x8 register-blocked FFMA2 GEMM (proven R12/R14 form) ------
__global__ __launch_bounds__(256, 2) void k_gemm(const float* __restrict__ xin_or_null,
                                                 int layer,
                                                 const float* __restrict__ as_g,
                                                 const float* __restrict__ ad_g) {
    __shared__ float sW[33 * 128];      // [k][o]
    __shared__ float sX[33 * 128];      // [k][node]
    __shared__ float sas[FD], sad[FD];

    const float* xin = xin_or_null ? xin_or_null : g_x2;
    const float* dn = (layer == 1) ? g_dn1 : g_dn2;
    const float* wq = (layer == 1) ? g_Wq : g_Wq2;
    float qs = 0.f;
    if (layer == 2) qs = fmaxf(__int_as_float(g_imax[0]), 1e-8f) * (1.f / 127.f);

    int t = threadIdx.x;
    int nb = blockIdx.x * 128;
    if (t < FD) { sas[t] = as_g[t]; sad[t] = ad_g[t]; }

    int tx = t & 15, ty = t >> 4;
    int ob = tx * 8;
    int nloc = ty * 8;

    unsigned long long acc[8][4];
#pragma unroll
    for (int i = 0; i < 8; i++)
#pragma unroll
        for (int p = 0; p < 4; p++) acc[i][p] = 0ull;

    for (int stage = 0; stage < 2; stage++) {
        if (stage) __syncthreads();
#pragma unroll
        for (int rep = 0; rep < 4; rep++) {
            int i = t + rep * 256;
            int o = i & 127, kq = i >> 7;
            float4 w4 = ((const float4*)wq)[o * 16 + stage * 8 + kq];
            sW[(kq*4+0)*128 + o] = w4.x;
            sW[(kq*4+1)*128 + o] = w4.y;
            sW[(kq*4+2)*128 + o] = w4.z;
            sW[(kq*4+3)*128 + o] = w4.w;
        }
#pragma unroll
        for (int rep = 0; rep < 4; rep++) {
            int i = t + rep * 256;
            int nl = i & 127, kq = i >> 7;
            int n = nb + nl;
            float4 v = make_float4(0.f, 0.f, 0.f, 0.f);
            if (n < NN) {
                v = ((const float4*)(xin + (size_t)n * KD))[stage * 8 + kq];
                if (layer == 2) {
                    float q;
                    q = rintf(v.x/qs); v.x = fmaxf(fminf(fmaxf(q,-128.f),127.f)*qs, 0.f);
                    q = rintf(v.y/qs); v.y = fmaxf(fminf(fmaxf(q,-128.f),127.f)*qs, 0.f);
                    q = rintf(v.z/qs); v.z = fmaxf(fminf(fmaxf(q,-128.f),127.f)*qs, 0.f);
                    q = rintf(v.w/qs); v.w = fmaxf(fminf(fmaxf(q,-128.f),127.f)*qs, 0.f);
                }
                float dd = dn[n];
                v.x *= dd; v.y *= dd; v.z *= dd; v.w *= dd;
            }
            sX[(kq*4+0)*128 + nl] = v.x;
            sX[(kq*4+1)*128 + nl] = v.y;
            sX[(kq*4+2)*128 + nl] = v.z;
            sX[(kq*4+3)*128 + nl] = v.w;
        }
        __syncthreads();

        float4 xa = *(const float4*)&sX[nloc];
        float4 xb = *(const float4*)&sX[nloc + 4];
        ulonglong2 wa = *(const ulonglong2*)&sW[ob];
        ulonglong2 wb = *(const ulonglong2*)&sW[ob + 4];

#pragma unroll 8
        for (int k = 0; k < 32; k++) {
            float4 xan = *(const float4*)&sX[(k+1)*128 + nloc];
            float4 xbn = *(const float4*)&sX[(k+1)*128 + nloc + 4];
            ulonglong2 wan = *(const ulonglong2*)&sW[(k+1)*128 + ob];
            ulonglong2 wbn = *(const ulonglong2*)&sW[(k+1)*128 + ob + 4];

            unsigned long long x0 = dup2(xa.x), x1 = dup2(xa.y);
            unsigned long long x2 = dup2(xa.z), x3 = dup2(xa.w);
            unsigned long long x4 = dup2(xb.x), x5 = dup2(xb.y);
            unsigned long long x6 = dup2(xb.z), x7 = dup2(xb.w);
            FMA2(acc[0][0], x0, wa.x, acc[0][0]); FMA2(acc[0][1], x0, wa.y, acc[0][1]);
            FMA2(acc[0][2], x0, wb.x, acc[0][2]); FMA2(acc[0][3], x0, wb.y, acc[0][3]);
            FMA2(acc[1][0], x1, wa.x, acc[1][0]); FMA2(acc[1][1], x1, wa.y, acc[1][1]);
            FMA2(acc[1][2], x1, wb.x, acc[1][2]); FMA2(acc[1][3], x1, wb.y, acc[1][3]);
            FMA2(acc[2][0], x2, wa.x, acc[2][0]); FMA2(acc[2][1], x2, wa.y, acc[2][1]);
            FMA2(acc[2][2], x2, wb.x, acc[2][2]); FMA2(acc[2][3], x2, wb.y, acc[2][3]);
            FMA2(acc[3][0], x3, wa.x, acc[3][0]); FMA2(acc[3][1], x3, wa.y, acc[3][1]);
            FMA2(acc[3][2], x3, wb.x, acc[3][2]); FMA2(acc[3][3], x3, wb.y, acc[3][3]);
            FMA2(acc[4][0], x4, wa.x, acc[4][0]); FMA2(acc[4][1], x4, wa.y, acc[4][1]);
            FMA2(acc[4][2], x4, wb.x, acc[4][2]); FMA2(acc[4][3], x4, wb.y, acc[4][3]);
            FMA2(acc[5][0], x5, wa.x, acc[5][0]); FMA2(acc[5][1], x5, wa.y, acc[5][1]);
            FMA2(acc[5][2], x5, wb.x, acc[5][2]); FMA2(acc[5][3], x5, wb.y, acc[5][3]);
            FMA2(acc[6][0], x6, wa.x, acc[6][0]); FMA2(acc[6][1], x6, wa.y, acc[6][1]);
            FMA2(acc[6][2], x6, wb.x, acc[6][2]); FMA2(acc[6][3], x6, wb.y, acc[6][3]);
            FMA2(acc[7][0], x7, wa.x, acc[7][0]); FMA2(acc[7][1], x7, wa.y, acc[7][1]);
            FMA2(acc[7][2], x7, wb.x, acc[7][2]); FMA2(acc[7][3], x7, wb.y, acc[7][3]);

            xa = xan; xb = xbn; wa = wan; wb = wbn;
        }
    }

    float av[8], dv[8];
#pragma unroll
    for (int j = 0; j < 8; j++) { av[j] = sas[ob + j]; dv[j] = sad[ob + j]; }

    float ps[8], pd[8];
#pragma unroll
    for (int i = 0; i < 8; i++) {
        int n = nb + nloc + i;
        float2 u0 = unpack2(acc[i][0]), u1 = unpack2(acc[i][1]);
        float2 u2 = unpack2(acc[i][2]), u3 = unpack2(acc[i][3]);
        if (n < NN) {
            float4* hp = (float4*)&g_h[(size_t)n * FD + ob];
            hp[0] = make_float4(u0.x, u0.y, u1.x, u1.y);
            hp[1] = make_float4(u2.x, u2.y, u3.x, u3.y);
        }
        ps[i] = u0.x*av[0] + u0.y*av[1] + u1.x*av[2] + u1.y*av[3]
              + u2.x*av[4] + u2.y*av[5] + u3.x*av[6] + u3.y*av[7];
        pd[i] = u0.x*dv[0] + u0.y*dv[1] + u1.x*dv[2] + u1.y*dv[3]
              + u2.x*dv[4] + u2.y*dv[5] + u3.x*dv[6] + u3.y*dv[7];
    }

#pragma unroll
    for (int o = 1; o <= 4; o <<= 1) {
#pragma unroll
        for (int i = 0; i < 8; i++) {
            ps[i] += __shfl_xor_sync(0xffffffffu, ps[i], o);
            pd[i] += __shfl_xor_sync(0xffffffffu, pd[i], o);
        }
    }
    if ((tx & 7) == 0) {
        int h = tx >> 3;
#pragma unroll
        for (int i = 0; i < 8; i++) {
            int n = nb + nloc + i;
            if (n < NN) { g_asrc[n*2+h] = ps[i]; g_adst[n*2+h] = pd[i]; }
        }
    }
}

// ---------------- gather: 2 nodes per warp (16-lane halves), 2-edge unroll ---
__global__ __launch_bounds__(256) void k_gather(int layer, const float* __restrict__ bias) {
    const float4* ed = (layer == 1) ? g_ed1 : g_ed2;
    int tid  = threadIdx.x;
    int warp = tid >> 5;
    int lane = tid & 31;
    int half = lane >> 4;
    int hl   = lane & 15;
    unsigned mask = half ? 0xffff0000u : 0x0000ffffu;
    int node = (blockIdx.x * 256 + tid) >> 4;
    int sbase = half * 16;

    __shared__ int   sm_s [8][32];
    __shared__ float sm_e0[8][32];
    __shared__ float sm_e1[8][32];

    int beg = g_doff[node];
    int deg = g_doff[node + 1] - beg;
    float2 ad = ((const float2*)g_adst)[node];

    float den0 = 0.f, den1 = 0.f;
    float4 A0 = make_float4(0.f, 0.f, 0.f, 0.f);
    float4 A1 = make_float4(0.f, 0.f, 0.f, 0.f);

    for (int base = 0; base < deg; base += 16) {
        int cnt = min(16, deg - base);
        int s = 0; float e0 = 0.f, e1 = 0.f;
        if (hl < cnt) {
            float4 er = ed[beg + base + hl];
            s = __float_as_int(er.x);
            float2 as = ((const float2*)g_asrc)[s];
            float x0 = as.x + ad.x + er.y; x0 = (x0 >= 0.f) ? x0 : 0.2f * x0;
            float x1 = as.y + ad.y + er.z; x1 = (x1 >= 0.f) ? x1 : 0.2f * x1;
            e0 = __expf(x0);
            e1 = __expf(x1);
        }
        den0 += e0; den1 += e1;
        sm_s [warp][sbase + hl] = s;
        sm_e0[warp][sbase + hl] = e0;
        sm_e1[warp][sbase + hl] = e1;
        __syncwarp(mask);
        int k = 0;
        for (; k + 2 <= cnt; k += 2) {
            int s0 = sm_s[warp][sbase + k];
            int s1 = sm_s[warp][sbase + k + 1];
            float w00 = sm_e0[warp][sbase + k],     w01 = sm_e1[warp][sbase + k];
            float w10 = sm_e0[warp][sbase + k + 1], w11 = sm_e1[warp][sbase + k + 1];
            const float4* hp0 = (const float4*)(g_h + (size_t)s0 * FD);
            const float4* hp1 = (const float4*)(g_h + (size_t)s1 * FD);
            float4 p0 = hp0[hl], q0 = hp0[16 + hl];
            float4 p1 = hp1[hl], q1 = hp1[16 + hl];
            A0.x += w00*p0.x + w10*p1.x; A0.y += w00*p0.y + w10*p1.y;
            A0.z += w00*p0.z + w10*p1.z; A0.w += w00*p0.w + w10*p1.w;
            A1.x += w01*q0.x + w11*q1.x; A1.y += w01*q0.y + w11*q1.y;
            A1.z += w01*q0.z + w11*q1.z; A1.w += w01*q0.w + w11*q1.w;
        }
        for (; k < cnt; k++) {
            int   sk = sm_s[warp][sbase + k];
            float w0 = sm_e0[warp][sbase + k], w1 = sm_e1[warp][sbase + k];
            const float4* hp = (const float4*)(g_h + (size_t)sk * FD);
            float4 p = hp[hl], q = hp[16 + hl];
            A0.x += w0*p.x; A0.y += w0*p.y; A0.z += w0*p.z; A0.w += w0*p.w;
            A1.x += w1*q.x; A1.y += w1*q.y; A1.z += w1*q.z; A1.w += w1*q.w;
        }
        __syncwarp(mask);
    }

#pragma unroll
    for (int o = 8; o; o >>= 1) {
        den0 += __shfl_xor_sync(mask, den0, o);
        den1 += __shfl_xor_sync(mask, den1, o);
    }
    float inv0 = 1.f / (den0 + 1e-16f);
    float inv1 = 1.f / (den1 + 1e-16f);

    float4 bb = ((const float4*)bias)[hl];
    float4 tv;
    tv.x = (A0.x * inv0 + A1.x * inv1) * 0.5f + bb.x;
    tv.y = (A0.y * inv0 + A1.y * inv1) * 0.5f + bb.y;
    tv.z = (A0.z * inv0 + A1.z * inv1) * 0.5f + bb.z;
    tv.w = (A0.w * inv0 + A1.w * inv1) * 0.5f + bb.w;
    ((float4*)(g_x2 + (size_t)node * KD))[hl] = tv;
    float mv = fmaxf(fmaxf(fabsf(tv.x), fabsf(tv.y)), fmaxf(fabsf(tv.z), fabsf(tv.w)));

    __syncwarp();
#pragma unroll
    for (int o = 16; o; o >>= 1) mv = fmaxf(mv, __shfl_xor_sync(0xffffffffu, mv, o));

    __shared__ float sred[8];
    if (lane == 0) sred[warp] = mv;
    __syncthreads();
    if (tid < 8) {
        float v = sred[tid];
#pragma unroll
        for (int o = 4; o; o >>= 1) v = fmaxf(v, __shfl_xor_sync(0xffu, v, o));
        if (tid == 0) atomicMax(&g_imax[layer - 1], __float_as_int(v));
    }
}

// ---------------- final per-tensor fake-quant (float4 vectorized) ------------
__global__ void k_fin_post(float4* __restrict__ out) {
    int i = blockIdx.x * blockDim.x + threadIdx.x;
    if (i >= NN * KD / 4) return;
    float s = fmaxf(__int_as_float(g_imax[1]), 1e-8f) * (1.f / 127.f);
    float4 v = ((const float4*)g_x2)[i];
    float q;
    q = rintf(v.x / s); v.x = fminf(fmaxf(q, -128.f), 127.f) * s;
    q = rintf(v.y / s); v.y = fminf(fmaxf(q, -128.f), 127.f) * s;
    q = rintf(v.z / s); v.z = fminf(fmaxf(q, -128.f), 127.f) * s;
    q = rintf(v.w / s); v.w = fminf(fmaxf(q, -128.f), 127.f) * s;
    out[i] = v;
}

// ---------------- host ------------------------------------------------------
extern "C" void kernel_launch(void* const* d_in, const int* in_sizes, int n_in,
                              void* d_out, int out_size) {
    const float* x    = (const float*)d_in[0];
    const int*   ei   = (const int*)d_in[1];
    const int*   src  = ei;
    const int*   dst  = ei + EE;
    const float* ea   = (const float*)d_in[2];
    const float* a1   = (const float*)d_in[3];
    const float* W1   = (const float*)d_in[4];
    const float* We1  = (const float*)d_in[5];
    const float* as1  = (const float*)d_in[6];
    const float* ad1  = (const float*)d_in[7];
    const float* ae1  = (const float*)d_in[8];
    const float* b1   = (const float*)d_in[9];
    const float* a2   = (const float*)d_in[10];
    const float* W2   = (const float*)d_in[11];
    const float* We2  = (const float*)d_in[12];
    const float* as2  = (const float*)d_in[13];
    const float* ad2  = (const float*)d_in[14];
    const float* ae2  = (const float*)d_in[15];
    const float* b2   = (const float*)d_in[16];
    float* out = (float*)d_out;

    const int TB = 256;
    int gN   = (NN + TB - 1) / TB;
    int gE   = (EE + TB - 1) / TB;
    int gGem = (NN + 127) / 128;
    int gGat = NN / 16;
    int gF4  = (NN * KD / 4 + TB - 1) / TB;

    cudaStream_t sB;
    cudaStreamCreateWithFlags(&sB, cudaStreamNonBlocking);
    cudaEvent_t evDeg, evB;
    cudaEventCreateWithFlags(&evDeg, cudaEventDisableTiming);
    cudaEventCreateWithFlags(&evB, cudaEventDisableTiming);

    // zero counters via memset nodes (capture-legal)
    int* dDegi; cudaGetSymbolAddress((void**)&dDegi, g_degi);
    int* dDcnt; cudaGetSymbolAddress((void**)&dDcnt, g_dcnt);
    int* dCur;  cudaGetSymbolAddress((void**)&dCur,  g_cur);
    cudaMemsetAsync(dDegi, 0, NN * sizeof(int), 0);
    cudaMemsetAsync(dDcnt, 0, NN * sizeof(int), 0);
    cudaMemsetAsync(dCur,  0, NN * sizeof(int), 0);

    // main stream: degree + layer-1 GEMM chain
    k_deg<<<gE, TB>>>(src, dst);
    cudaEventRecord(evDeg, 0);
    cudaStreamWaitEvent(sB, evDeg, 0);

    k_prep<<<gN + 1, TB>>>(a1, a2, W1, gN);
    k_gemm<<<gGem, 256>>>(x, 1, as1, ad1);              // profile anchor

    // branch B (concurrent with prep+gemm1)
    k_scan1<<<SCB, 256, 0, sB>>>();
    k_scan2<<<1, 128, 0, sB>>>();
    k_scan3<<<SCB, 256, 0, sB>>>();
    k_edgepre<<<gE, TB, 0, sB>>>(ea, src, dst, We1, ae1, We2, ae2);
    k_quantW2<<<1, 256, 0, sB>>>(W2, 1);
    cudaEventRecord(evB, sB);

    cudaStreamWaitEvent(0, evB, 0);
    k_gather<<<gGat, 256>>>(1, b1);
    k_gemm<<<gGem, 256>>>(nullptr, 2, as2, ad2);
    k_gather<<<gGat, 256>>>(2, b2);
    k_fin_post<<<gF4, TB>>>((float4*)out);
}